// round 1
// baseline (speedup 1.0000x reference)
#include <cuda_runtime.h>

// VectorQuantizer: x [8,2048,512] fp32, codebook [8,1024,64] fp32
// out[b,s,g*64+k] = x + (codebook[g, argmin_k dist] - x)   (fp32, same order as ref)
//
// argmin_k ||x - c_k||^2  ==  argmax_k ( (2x)·c_k - ||c_k||^2 )
//
// CTA: 64 tokens x 1 group, loops over 16 chunks of 64 codes.
// Thread tile 4 tokens x 4 codes, K=64 fully unrolled.

#define NUM_TOKENS 16384
#define DFULL      512
#define DG         64          // per-group dim
#define KCODES     1024
#define NGROUPS    8
#define MTILE      64          // tokens per block
#define NTILE      64          // codes per chunk
#define NCHUNK     (KCODES / NTILE)
#define PITCH      68          // smem row pitch in floats (mult of 4, avoids conflicts)

__global__ __launch_bounds__(256, 2)
void vq_kernel(const float* __restrict__ x,
               const float* __restrict__ cb,
               float* __restrict__ out)
{
    const int g   = blockIdx.y;
    const int t0  = blockIdx.x * MTILE;
    const int tid = threadIdx.x;

    __shared__ float xs[DG * PITCH];      // xs[k*PITCH + tok] = 2*x
    __shared__ float cs[DG * PITCH];      // cs[k*PITCH + code]
    __shared__ float cn[NTILE];           // ||c||^2 per code in chunk
    __shared__ float sval[MTILE * 16];
    __shared__ int   sidx[MTILE * 16];
    __shared__ int   fin[MTILE];

    // ---- load x tile (scaled by 2) transposed into xs ----
    {
        const int tok  = tid >> 2;        // 0..63
        const int part = tid & 3;         // 0..3 (16 floats each)
        const float* xp = x + (size_t)(t0 + tok) * DFULL + g * DG + part * 16;
        #pragma unroll
        for (int q = 0; q < 4; q++) {
            float4 v = *(const float4*)(xp + q * 4);
            int k = part * 16 + q * 4;
            xs[(k + 0) * PITCH + tok] = 2.0f * v.x;
            xs[(k + 1) * PITCH + tok] = 2.0f * v.y;
            xs[(k + 2) * PITCH + tok] = 2.0f * v.z;
            xs[(k + 3) * PITCH + tok] = 2.0f * v.w;
        }
    }

    const int tr = tid >> 4;   // 0..15 : token group (4 tokens)
    const int tc = tid & 15;   // 0..15 : code group  (4 codes)

    float best[4];
    int   bidx[4];
    #pragma unroll
    for (int i = 0; i < 4; i++) { best[i] = -1e30f; bidx[i] = 0; }

    const float* cbg = cb + (size_t)g * KCODES * DG;

    for (int ch = 0; ch < NCHUNK; ch++) {
        const int c0 = ch * NTILE;
        __syncthreads();   // previous chunk's readers done before overwriting cs/cn

        // ---- load codebook chunk transposed into cs ----
        {
            const int code = tid >> 2;
            const int part = tid & 3;
            const float* cp = cbg + (size_t)(c0 + code) * DG + part * 16;
            #pragma unroll
            for (int q = 0; q < 4; q++) {
                float4 v = *(const float4*)(cp + q * 4);
                int k = part * 16 + q * 4;
                cs[(k + 0) * PITCH + code] = v.x;
                cs[(k + 1) * PITCH + code] = v.y;
                cs[(k + 2) * PITCH + code] = v.z;
                cs[(k + 3) * PITCH + code] = v.w;
            }
        }
        __syncthreads();

        // ---- code norms (2 warps; conflict-free column reads) ----
        if (tid < NTILE) {
            float s = 0.f;
            #pragma unroll
            for (int k = 0; k < DG; k++) {
                float v = cs[k * PITCH + tid];
                s += v * v;
            }
            cn[tid] = s;
        }

        // ---- main GEMM-like tile: acc[i][j] = sum_k (2x_i[k]) * c_j[k] ----
        float acc[4][4];
        #pragma unroll
        for (int i = 0; i < 4; i++)
            #pragma unroll
            for (int j = 0; j < 4; j++)
                acc[i][j] = 0.f;

        #pragma unroll
        for (int k = 0; k < DG; k++) {
            float4 xv = *(const float4*)&xs[k * PITCH + tr * 4];
            float4 cv = *(const float4*)&cs[k * PITCH + tc * 4];
            acc[0][0] += xv.x * cv.x; acc[0][1] += xv.x * cv.y;
            acc[0][2] += xv.x * cv.z; acc[0][3] += xv.x * cv.w;
            acc[1][0] += xv.y * cv.x; acc[1][1] += xv.y * cv.y;
            acc[1][2] += xv.y * cv.z; acc[1][3] += xv.y * cv.w;
            acc[2][0] += xv.z * cv.x; acc[2][1] += xv.z * cv.y;
            acc[2][2] += xv.z * cv.z; acc[2][3] += xv.z * cv.w;
            acc[3][0] += xv.w * cv.x; acc[3][1] += xv.w * cv.y;
            acc[3][2] += xv.w * cv.z; acc[3][3] += xv.w * cv.w;
        }

        __syncthreads();   // cn ready for everyone

        // ---- fold in -||c||^2, track running argmax (first-occurrence ties) ----
        #pragma unroll
        for (int j = 0; j < 4; j++) {
            const float c_n  = cn[tc * 4 + j];
            const int   code = c0 + tc * 4 + j;
            #pragma unroll
            for (int i = 0; i < 4; i++) {
                float s = acc[i][j] - c_n;
                if (s > best[i]) { best[i] = s; bidx[i] = code; }
            }
        }
    }

    // ---- cross-thread argmax reduction (16 code-columns per token) ----
    #pragma unroll
    for (int i = 0; i < 4; i++) {
        sval[(tr * 4 + i) * 16 + tc] = best[i];
        sidx[(tr * 4 + i) * 16 + tc] = bidx[i];
    }
    __syncthreads();
    if (tid < MTILE) {
        float bv = sval[tid * 16];
        int   bi = sidx[tid * 16];
        #pragma unroll
        for (int c = 1; c < 16; c++) {
            float v  = sval[tid * 16 + c];
            int   ix = sidx[tid * 16 + c];
            // exact tie -> smaller code index (matches jnp.argmin first occurrence)
            if (v > bv || (v == bv && ix < bi)) { bv = v; bi = ix; }
        }
        fin[tid] = bi;
    }
    __syncthreads();

    // ---- gather winning code, emit out = x + (c - x) in ref's fp32 order ----
    {
        const int tok  = tid >> 2;
        const int part = tid & 3;
        const int code = fin[tok];
        const float* cp = cbg + (size_t)code * DG + part * 16;
        const float* xp = x   + (size_t)(t0 + tok) * DFULL + g * DG + part * 16;
        float*       op = out + (size_t)(t0 + tok) * DFULL + g * DG + part * 16;
        #pragma unroll
        for (int q = 0; q < 4; q++) {
            float4 c4 = *(const float4*)(cp + q * 4);
            float4 x4 = *(const float4*)(xp + q * 4);
            float4 o;
            o.x = x4.x + (c4.x - x4.x);
            o.y = x4.y + (c4.y - x4.y);
            o.z = x4.z + (c4.z - x4.z);
            o.w = x4.w + (c4.w - x4.w);
            *(float4*)(op + q * 4) = o;
        }
    }
}

extern "C" void kernel_launch(void* const* d_in, const int* in_sizes, int n_in,
                              void* d_out, int out_size)
{
    const float* x  = (const float*)d_in[0];   // [8,2048,512]
    const float* cb = (const float*)d_in[1];   // [8,1024,64]
    float* out = (float*)d_out;

    dim3 grid(NUM_TOKENS / MTILE, NGROUPS);    // (256, 8)
    vq_kernel<<<grid, 256>>>(x, cb, out);
}

// round 4
// speedup vs baseline: 1.3131x; 1.3131x over previous
#include <cuda_runtime.h>

// VectorQuantizer: x [8,2048,512] fp32, codebook [8,1024,64] fp32
// out[b,s,g*64+:64] = x + (codebook[g, argmin_k ||x-c_k||^2] - x)
//
// argmin_k ||x - c_k||^2  ==  argmax_k ( (2x)·c_k - ||c_k||^2 )
//
// CTA: 128 tokens x 1 group, 8 chunks of 128 codes. Thread tile 8x8.
// Thread's tokens = {tr*4+i, 64+tr*4+i}, codes = {tc*4+j, 64+tc*4+j}
// (split-float4 pattern -> conflict-free LDS.128).

#define NUM_TOKENS 16384
#define DFULL      512
#define DG         64
#define KCODES     1024
#define NGROUPS    8
#define MTILE      128
#define NTILE      128
#define NCHUNK     (KCODES / NTILE)
#define PITCH      132          // smem row pitch in floats (128 + 4)

// dynamic smem layout (floats):
//  xs   : 64*PITCH          (8448)   xs[k*PITCH + tok] = 2*x
//  cs   : 64*PITCH          (8448)   cs[k*PITCH + code]
//  cn   : 128                        ||c||^2 per code in chunk
//  sval : 128*16            (2048)
//  sidx : 128*16            (2048)
//  fin  : 128
#define SMEM_FLOATS (64*PITCH + 64*PITCH + 128 + 2048 + 2048 + 128)
#define SMEM_BYTES  (SMEM_FLOATS * 4)

extern __shared__ float smem_dyn[];

__global__ __launch_bounds__(256, 2)
void vq_kernel(const float* __restrict__ x,
               const float* __restrict__ cb,
               float* __restrict__ out)
{
    float* xs   = smem_dyn;
    float* cs   = xs + 64 * PITCH;
    float* cn   = cs + 64 * PITCH;
    float* sval = cn + 128;
    int*   sidx = (int*)(sval + 2048);
    int*   fin  = sidx + 2048;

    const int g   = blockIdx.y;
    const int t0  = blockIdx.x * MTILE;
    const int tid = threadIdx.x;

    // ---- load x tile (scaled by 2), transposed: xs[k][tok] ----
    {
        const int tok  = tid >> 1;          // 0..127
        const int part = tid & 1;           // 0/1 : 32 floats each
        const float* xp = x + (size_t)(t0 + tok) * DFULL + g * DG + part * 32;
        #pragma unroll
        for (int q = 0; q < 8; q++) {
            float4 v = *(const float4*)(xp + q * 4);
            int k = part * 32 + q * 4;
            xs[(k + 0) * PITCH + tok] = 2.0f * v.x;
            xs[(k + 1) * PITCH + tok] = 2.0f * v.y;
            xs[(k + 2) * PITCH + tok] = 2.0f * v.z;
            xs[(k + 3) * PITCH + tok] = 2.0f * v.w;
        }
    }

    const int tr = tid >> 4;   // 0..15 : token group
    const int tc = tid & 15;   // 0..15 : code group

    float best[8];
    int   bidx[8];
    #pragma unroll
    for (int i = 0; i < 8; i++) { best[i] = -1e30f; bidx[i] = 0; }

    const float* cbg = cb + (size_t)g * KCODES * DG;

    for (int ch = 0; ch < NCHUNK; ch++) {
        const int c0 = ch * NTILE;
        __syncthreads();   // previous chunk fully consumed before overwrite

        // ---- load codebook chunk, transposed: cs[k][code] ----
        {
            const int code = tid >> 1;
            const int part = tid & 1;
            const float* cp = cbg + (size_t)(c0 + code) * DG + part * 32;
            #pragma unroll
            for (int q = 0; q < 8; q++) {
                float4 v = *(const float4*)(cp + q * 4);
                int k = part * 32 + q * 4;
                cs[(k + 0) * PITCH + code] = v.x;
                cs[(k + 1) * PITCH + code] = v.y;
                cs[(k + 2) * PITCH + code] = v.z;
                cs[(k + 3) * PITCH + code] = v.w;
            }
        }
        __syncthreads();

        // ---- code norms (first 4 warps; conflict-free column reads) ----
        if (tid < NTILE) {
            float s = 0.f;
            #pragma unroll 8
            for (int k = 0; k < DG; k++) {
                float v = cs[k * PITCH + tid];
                s += v * v;
            }
            cn[tid] = s;
        }

        // ---- 8x8 register tile: acc[i][j] = sum_k (2x_i[k]) * c_j[k] ----
        float acc[8][8];
        #pragma unroll
        for (int i = 0; i < 8; i++)
            #pragma unroll
            for (int j = 0; j < 8; j++)
                acc[i][j] = 0.f;

        {
            const float* xrow = xs + tr * 4;
            const float* crow = cs + tc * 4;
            #pragma unroll 8
            for (int k = 0; k < DG; k++) {
                float4 xa = *(const float4*)(xrow + k * PITCH);
                float4 xb = *(const float4*)(xrow + k * PITCH + 64);
                float4 ca = *(const float4*)(crow + k * PITCH);
                float4 cbv = *(const float4*)(crow + k * PITCH + 64);
                float xv[8] = {xa.x, xa.y, xa.z, xa.w, xb.x, xb.y, xb.z, xb.w};
                float cv[8] = {ca.x, ca.y, ca.z, ca.w, cbv.x, cbv.y, cbv.z, cbv.w};
                #pragma unroll
                for (int i = 0; i < 8; i++)
                    #pragma unroll
                    for (int j = 0; j < 8; j++)
                        acc[i][j] += xv[i] * cv[j];
            }
        }

        __syncthreads();   // cn ready

        // ---- fold -||c||^2, running argmax (first-occurrence ties) ----
        #pragma unroll
        for (int j = 0; j < 8; j++) {
            const int cl   = (j < 4) ? (tc * 4 + j) : (64 + tc * 4 + (j - 4));
            const float c_n = cn[cl];
            const int  code = c0 + cl;
            #pragma unroll
            for (int i = 0; i < 8; i++) {
                float s = acc[i][j] - c_n;
                if (s > best[i]) { best[i] = s; bidx[i] = code; }
            }
        }
    }

    // ---- cross-thread argmax reduction (16 candidates per token) ----
    #pragma unroll
    for (int i = 0; i < 8; i++) {
        const int tl = (i < 4) ? (tr * 4 + i) : (64 + tr * 4 + (i - 4));
        sval[tl * 16 + tc] = best[i];
        sidx[tl * 16 + tc] = bidx[i];
    }
    __syncthreads();
    if (tid < MTILE) {
        float bv = sval[tid * 16];
        int   bi = sidx[tid * 16];
        #pragma unroll
        for (int c = 1; c < 16; c++) {
            float v  = sval[tid * 16 + c];
            int   ix = sidx[tid * 16 + c];
            // exact tie -> smaller code index (jnp.argmin first occurrence)
            if (v > bv || (v == bv && ix < bi)) { bv = v; bi = ix; }
        }
        fin[tid] = bi;
    }
    __syncthreads();

    // ---- gather winning code, out = x + (c - x), ref fp32 op order ----
    {
        const int tok  = tid >> 1;
        const int part = tid & 1;
        const int code = fin[tok];
        const float* cp = cbg + (size_t)code * DG + part * 32;
        const float* xp = x   + (size_t)(t0 + tok) * DFULL + g * DG + part * 32;
        float*       op = out + (size_t)(t0 + tok) * DFULL + g * DG + part * 32;
        #pragma unroll
        for (int q = 0; q < 8; q++) {
            float4 c4 = *(const float4*)(cp + q * 4);
            float4 x4 = *(const float4*)(xp + q * 4);
            float4 o;
            o.x = x4.x + (c4.x - x4.x);
            o.y = x4.y + (c4.y - x4.y);
            o.z = x4.z + (c4.z - x4.z);
            o.w = x4.w + (c4.w - x4.w);
            *(float4*)(op + q * 4) = o;
        }
    }
}

extern "C" void kernel_launch(void* const* d_in, const int* in_sizes, int n_in,
                              void* d_out, int out_size)
{
    const float* x  = (const float*)d_in[0];   // [8,2048,512]
    const float* cb = (const float*)d_in[1];   // [8,1024,64]
    float* out = (float*)d_out;

    static int configured = 0;
    if (!configured) {
        cudaFuncSetAttribute(vq_kernel,
                             cudaFuncAttributeMaxDynamicSharedMemorySize,
                             SMEM_BYTES);
        configured = 1;
    }

    dim3 grid(NUM_TOKENS / MTILE, NGROUPS);    // (128, 8)
    vq_kernel<<<grid, 256, SMEM_BYTES>>>(x, cb, out);
}

// round 10
// speedup vs baseline: 1.4272x; 1.0869x over previous
#include <cuda_runtime.h>
#include <cstdint>

// VectorQuantizer: x [8,2048,512] fp32, codebook [8,1024,64] fp32
// out[b,s,g*64+:64] = x + (codebook[g, argmin_k ||x-c_k||^2] - x)
//
// argmin_k ||x - c_k||^2  ==  argmax_k ( (2x)·c_k - ||c_k||^2 )
//
// CTA: 128 tokens x 1 group, 8 chunks of 128 codes. Thread tile 8x8.
// Inner product uses packed fma.rn.f32x2 (FFMA2): token pairs packed in
// b64 regs (free from LDS.128 register pairs), code value duplicated into
// both halves. Exact fp32 per lane -> bitwise-identical argmin scores.

#define NUM_TOKENS 16384
#define DFULL      512
#define DG         64
#define KCODES     1024
#define NGROUPS    8
#define MTILE      128
#define NTILE      128
#define NCHUNK     (KCODES / NTILE)
#define PITCH      132          // smem row pitch in floats (128 + 4), 16B-aligned rows

// dynamic smem layout (floats):
//  xs   : 64*PITCH   xs[k*PITCH + tok] = 2*x
//  cs   : 64*PITCH   cs[k*PITCH + code]
//  cn   : 128        ||c||^2 per code in chunk
//  sval : 128*16
//  sidx : 128*16
//  fin  : 128
#define SMEM_FLOATS (64*PITCH + 64*PITCH + 128 + 2048 + 2048 + 128)
#define SMEM_BYTES  (SMEM_FLOATS * 4)

extern __shared__ float smem_dyn[];

__device__ __forceinline__ unsigned long long dupf2(float v) {
    unsigned long long r;
    unsigned u = __float_as_uint(v);
    asm("mov.b64 %0, {%1, %1};" : "=l"(r) : "r"(u));
    return r;
}

__device__ __forceinline__ void ffma2(unsigned long long& acc,
                                      unsigned long long a,
                                      unsigned long long b) {
    asm("fma.rn.f32x2 %0, %1, %2, %0;" : "+l"(acc) : "l"(a), "l"(b));
}

__device__ __forceinline__ void unpack2(unsigned long long p, float& lo, float& hi) {
    unsigned ulo, uhi;
    asm("mov.b64 {%0, %1}, %2;" : "=r"(ulo), "=r"(uhi) : "l"(p));
    lo = __uint_as_float(ulo);
    hi = __uint_as_float(uhi);
}

__global__ __launch_bounds__(256, 2)
void vq_kernel(const float* __restrict__ x,
               const float* __restrict__ cb,
               float* __restrict__ out)
{
    float* xs   = smem_dyn;
    float* cs   = xs + 64 * PITCH;
    float* cn   = cs + 64 * PITCH;
    float* sval = cn + 128;
    int*   sidx = (int*)(sval + 2048);
    int*   fin  = sidx + 2048;

    const int g   = blockIdx.y;
    const int t0  = blockIdx.x * MTILE;
    const int tid = threadIdx.x;

    // ---- load x tile (scaled by 2), transposed: xs[k][tok] ----
    {
        const int tok  = tid >> 1;          // 0..127
        const int part = tid & 1;           // 0/1 : 32 floats each
        const float* xp = x + (size_t)(t0 + tok) * DFULL + g * DG + part * 32;
        #pragma unroll
        for (int q = 0; q < 8; q++) {
            float4 v = *(const float4*)(xp + q * 4);
            int k = part * 32 + q * 4;
            xs[(k + 0) * PITCH + tok] = 2.0f * v.x;
            xs[(k + 1) * PITCH + tok] = 2.0f * v.y;
            xs[(k + 2) * PITCH + tok] = 2.0f * v.z;
            xs[(k + 3) * PITCH + tok] = 2.0f * v.w;
        }
    }

    const int tr = tid >> 4;   // 0..15 : token group
    const int tc = tid & 15;   // 0..15 : code group

    float best[8];
    int   bidx[8];
    #pragma unroll
    for (int i = 0; i < 8; i++) { best[i] = -1e30f; bidx[i] = 0; }

    const float* cbg = cb + (size_t)g * KCODES * DG;

    for (int ch = 0; ch < NCHUNK; ch++) {
        const int c0 = ch * NTILE;
        __syncthreads();   // previous chunk fully consumed before overwrite

        // ---- load codebook chunk, transposed: cs[k][code] ----
        {
            const int code = tid >> 1;
            const int part = tid & 1;
            const float* cp = cbg + (size_t)(c0 + code) * DG + part * 32;
            #pragma unroll
            for (int q = 0; q < 8; q++) {
                float4 v = *(const float4*)(cp + q * 4);
                int k = part * 32 + q * 4;
                cs[(k + 0) * PITCH + code] = v.x;
                cs[(k + 1) * PITCH + code] = v.y;
                cs[(k + 2) * PITCH + code] = v.z;
                cs[(k + 3) * PITCH + code] = v.w;
            }
        }
        __syncthreads();

        // ---- code norms (first 4 warps; conflict-free column reads) ----
        if (tid < NTILE) {
            float s = 0.f;
            #pragma unroll 8
            for (int k = 0; k < DG; k++) {
                float v = cs[k * PITCH + tid];
                s += v * v;
            }
            cn[tid] = s;
        }

        // ---- 8x8 tile via FFMA2: acc2[i2][j] = packed pair of tokens ----
        // token pairs: i2=0 -> (tr*4+0, tr*4+1), i2=1 -> (tr*4+2, tr*4+3),
        //              i2=2 -> (64+tr*4+0, 64+tr*4+1), i2=3 -> (64+tr*4+2, +3)
        unsigned long long acc2[4][8];
        #pragma unroll
        for (int i = 0; i < 4; i++)
            #pragma unroll
            for (int j = 0; j < 8; j++)
                acc2[i][j] = 0ull;   // two packed +0.0f

        {
            const float* xrow = xs + tr * 4;
            const float* crow = cs + tc * 4;
            #pragma unroll 8
            for (int k = 0; k < DG; k++) {
                // 16B loads; .x/.y are (f0,f1),(f2,f3) packed pairs for free
                ulonglong2 xA = *(const ulonglong2*)(xrow + k * PITCH);
                ulonglong2 xB = *(const ulonglong2*)(xrow + k * PITCH + 64);
                float4 ca  = *(const float4*)(crow + k * PITCH);
                float4 cbv = *(const float4*)(crow + k * PITCH + 64);

                unsigned long long xp4[4] = { xA.x, xA.y, xB.x, xB.y };
                unsigned long long cd[8];
                cd[0] = dupf2(ca.x);  cd[1] = dupf2(ca.y);
                cd[2] = dupf2(ca.z);  cd[3] = dupf2(ca.w);
                cd[4] = dupf2(cbv.x); cd[5] = dupf2(cbv.y);
                cd[6] = dupf2(cbv.z); cd[7] = dupf2(cbv.w);

                #pragma unroll
                for (int i = 0; i < 4; i++)
                    #pragma unroll
                    for (int j = 0; j < 8; j++)
                        ffma2(acc2[i][j], xp4[i], cd[j]);
            }
        }

        __syncthreads();   // cn ready

        // ---- fold -||c||^2, running argmax (first-occurrence ties) ----
        #pragma unroll
        for (int j = 0; j < 8; j++) {
            const int cl    = (j < 4) ? (tc * 4 + j) : (64 + tc * 4 + (j - 4));
            const float c_n = cn[cl];
            const int  code = c0 + cl;
            #pragma unroll
            for (int i2 = 0; i2 < 4; i2++) {
                float lo, hi;
                unpack2(acc2[i2][j], lo, hi);
                // token index within best[]: i2 pairs map to tokens in order
                const int ib = i2 * 2;     // 0,2,4,6
                float s0 = lo - c_n;
                float s1 = hi - c_n;
                if (s0 > best[ib])     { best[ib]     = s0; bidx[ib]     = code; }
                if (s1 > best[ib + 1]) { best[ib + 1] = s1; bidx[ib + 1] = code; }
            }
        }
    }

    // ---- cross-thread argmax reduction (16 candidates per token) ----
    // best[i]: i<4 -> token tr*4+i ; i>=4 -> token 64+tr*4+(i-4)
    #pragma unroll
    for (int i = 0; i < 8; i++) {
        const int tl = (i < 4) ? (tr * 4 + i) : (64 + tr * 4 + (i - 4));
        sval[tl * 16 + tc] = best[i];
        sidx[tl * 16 + tc] = bidx[i];
    }
    __syncthreads();
    if (tid < MTILE) {
        float bv = sval[tid * 16];
        int   bi = sidx[tid * 16];
        #pragma unroll
        for (int c = 1; c < 16; c++) {
            float v  = sval[tid * 16 + c];
            int   ix = sidx[tid * 16 + c];
            // exact tie -> smaller code index (jnp.argmin first occurrence)
            if (v > bv || (v == bv && ix < bi)) { bv = v; bi = ix; }
        }
        fin[tid] = bi;
    }
    __syncthreads();

    // ---- gather winning code, out = x + (c - x), ref fp32 op order ----
    {
        const int tok  = tid >> 1;
        const int part = tid & 1;
        const int code = fin[tok];
        const float* cp = cbg + (size_t)code * DG + part * 32;
        const float* xp = x   + (size_t)(t0 + tok) * DFULL + g * DG + part * 32;
        float*       op = out + (size_t)(t0 + tok) * DFULL + g * DG + part * 32;
        #pragma unroll
        for (int q = 0; q < 8; q++) {
            float4 c4 = *(const float4*)(cp + q * 4);
            float4 x4 = *(const float4*)(xp + q * 4);
            float4 o;
            o.x = x4.x + (c4.x - x4.x);
            o.y = x4.y + (c4.y - x4.y);
            o.z = x4.z + (c4.z - x4.z);
            o.w = x4.w + (c4.w - x4.w);
            *(float4*)(op + q * 4) = o;
        }
    }
}

extern "C" void kernel_launch(void* const* d_in, const int* in_sizes, int n_in,
                              void* d_out, int out_size)
{
    const float* x  = (const float*)d_in[0];   // [8,2048,512]
    const float* cb = (const float*)d_in[1];   // [8,1024,64]
    float* out = (float*)d_out;

    static int configured = 0;
    if (!configured) {
        cudaFuncSetAttribute(vq_kernel,
                             cudaFuncAttributeMaxDynamicSharedMemorySize,
                             SMEM_BYTES);
        configured = 1;
    }

    dim3 grid(NUM_TOKENS / MTILE, NGROUPS);    // (128, 8)
    vq_kernel<<<grid, 256, SMEM_BYTES>>>(x, cb, out);
}